// round 9
// baseline (speedup 1.0000x reference)
#include <cuda_runtime.h>
#include <cstdint>
#include <math.h>

// Problem constants (fixed shapes)
#define N_ST   2048
#define N_OBS  8192
#define T_LEN  8192

#define N_BLOCKS        128
#define COLS_PER_BLOCK  16          // 2048 / 128
#define THREADS         256
#define KITER           32          // j-values per thread (32 * 64 stripes = 2048)
#define EPT             8           // elements polled per thread (2048/256)

// ---- persistent device scratch (no allocations allowed) ----
__device__ float              g_Bobs[(size_t)T_LEN * N_ST];   // 64 MB
__device__ unsigned long long g_alpha2[2][N_ST];              // {tag:u32 | value:f32}
__device__ unsigned int       g_epoch;                        // bumped once per launch

// ---------------------------------------------------------------------------
// Scalar morally-strong 8B accessors (single-copy atomic per PTX memory model)
// ---------------------------------------------------------------------------
__device__ __forceinline__ unsigned long long ld_relaxed_u64(const unsigned long long* p) {
    unsigned long long v;
    asm volatile("ld.relaxed.gpu.global.b64 %0, [%1];" : "=l"(v) : "l"(p));
    return v;
}
__device__ __forceinline__ void st_relaxed_u64(unsigned long long* p, unsigned long long v) {
    asm volatile("st.relaxed.gpu.global.b64 [%0], %1;" :: "l"(p), "l"(v) : "memory");
}
__device__ __forceinline__ unsigned long long pack_val_tag(float v, unsigned int tag) {
    return ((unsigned long long)tag << 32) | (unsigned long long)__float_as_uint(v);
}

// ---------------------------------------------------------------------------
// Kernel 1: gather emissions + bump epoch
// ---------------------------------------------------------------------------
__global__ void gather_bobs(const float* __restrict__ B, const int* __restrict__ se) {
    if (blockIdx.x == 0 && threadIdx.x == 0) g_epoch = g_epoch + 1u;
    size_t idx    = (size_t)blockIdx.x * blockDim.x + threadIdx.x;
    size_t stride = (size_t)gridDim.x * blockDim.x;
    const size_t total = (size_t)T_LEN * N_ST;
    for (; idx < total; idx += stride) {
        int t = (int)(idx >> 11);
        int i = (int)(idx & (N_ST - 1));
        g_Bobs[idx] = B[(size_t)i * N_OBS + se[t]];
    }
}

// ---------------------------------------------------------------------------
// Kernel 2: persistent forward recursion, tag-in-data sync with EARLY-EXIT
// coalesced polling. CTA b owns columns [16b, 16b+16). A-slice in registers.
// ---------------------------------------------------------------------------
__global__ void __launch_bounds__(THREADS, 1)
hmm_forward(const float* __restrict__ Pi0,
            const float* __restrict__ A,
            float* __restrict__ out)
{
    __shared__ float alpha_s[N_ST];
    __shared__ float red_s[8 * COLS_PER_BLOCK];   // [warp][16 cols]

    const int tid     = threadIdx.x;
    const int b       = blockIdx.x;
    const int colbase = b * COLS_PER_BLOCK;
    const int lane    = tid & 31;
    const int warp    = tid >> 5;
    const int c       = tid & 3;    // float4 column group (cols 4c..4c+3)
    const int s       = tid >> 2;   // j-stripe id, 0..63

    const unsigned int base = g_epoch << 13;      // epoch * 8192
    const int pbase = warp * (EPT * 32) + lane;   // poll base: coalesced per warp

    // ---- one-time: load A slice into registers ----
    float4 Areg[KITER];
    #pragma unroll
    for (int k = 0; k < KITER; ++k) {
        int j = s + (k << 6);
        Areg[k] = *(const float4*)(A + (size_t)j * N_ST + colbase + (c << 2));
    }

    // ---- step 0: alpha0 = Pi0 * Bobs[0], tag = base+0 ----
    if (tid < COLS_PER_BLOCK) {
        int i = colbase + tid;
        st_relaxed_u64(&g_alpha2[0][i], pack_val_tag(Pi0[i] * g_Bobs[i], base));
    }

    // ---- steps 1 .. T-1 ----
    for (int t = 1; t < T_LEN; ++t) {
        // emission weights (independent of alpha) -> issue early
        float bt = 0.0f;
        if (tid < COLS_PER_BLOCK)
            bt = __ldg(&g_Bobs[(size_t)t * N_ST + colbase + tid]);

        // ---- early-exit poll of alpha_{t-1}: tag+value in one 8B word ----
        {
            const unsigned int want = base + (unsigned int)(t - 1);
            const unsigned long long* src = g_alpha2[(t - 1) & 1];
            float vals[EPT];
            unsigned int done = 0;                 // 8 bits
            do {
                #pragma unroll
                for (int i = 0; i < EPT; ++i) {
                    if (!((done >> i) & 1u)) {
                        unsigned long long w = ld_relaxed_u64(src + pbase + i * 32);
                        if ((unsigned int)(w >> 32) == want) {
                            vals[i] = __uint_as_float((unsigned int)w);
                            done |= (1u << i);
                        }
                    }
                }
            } while (done != 0xFFu);
            #pragma unroll
            for (int i = 0; i < EPT; ++i)
                alpha_s[pbase + i * 32] = vals[i];
        }
        __syncthreads();

        // ---- matvec partial (R3-proven): acc[e] += alpha[s+64k]*A[s+64k][4c+e]
        float4 acc = make_float4(0.f, 0.f, 0.f, 0.f);
        #pragma unroll
        for (int k = 0; k < KITER; ++k) {
            float a = alpha_s[s + (k << 6)];
            acc.x = fmaf(a, Areg[k].x, acc.x);
            acc.y = fmaf(a, Areg[k].y, acc.y);
            acc.z = fmaf(a, Areg[k].z, acc.z);
            acc.w = fmaf(a, Areg[k].w, acc.w);
        }

        // reduce across the 8 lanes sharing the same c (xor 4,8,16)
        #pragma unroll
        for (int off = 4; off < 32; off <<= 1) {
            acc.x += __shfl_xor_sync(0xffffffffu, acc.x, off);
            acc.y += __shfl_xor_sync(0xffffffffu, acc.y, off);
            acc.z += __shfl_xor_sync(0xffffffffu, acc.z, off);
            acc.w += __shfl_xor_sync(0xffffffffu, acc.w, off);
        }
        if (lane < 4) {   // lane == c here
            int o = (warp << 4) + (lane << 2);
            red_s[o + 0] = acc.x;
            red_s[o + 1] = acc.y;
            red_s[o + 2] = acc.z;
            red_s[o + 3] = acc.w;
        }
        __syncthreads();

        // final per-column sum over 8 warps, apply emission, publish with tag.
        // (No trailing barrier: next iteration's post-staging barrier orders
        //  red_s reuse; alpha_s overwrite is safe once FMA consumers passed
        //  the barrier above.)
        if (tid < COLS_PER_BLOCK) {
            float sum = 0.f;
            #pragma unroll
            for (int w = 0; w < 8; ++w) sum += red_s[(w << 4) + tid];
            st_relaxed_u64(&g_alpha2[t & 1][colbase + tid],
                           pack_val_tag(sum * bt, base + (unsigned int)t));
        }
    }

    // ---- final reduction by CTA 0 ----
    if (b == 0) {
        const unsigned int want = base + (unsigned int)(T_LEN - 1);
        const unsigned long long* src = g_alpha2[(T_LEN - 1) & 1];
        float ssum = 0.f;
        {
            float vals[EPT];
            unsigned int done = 0;
            do {
                #pragma unroll
                for (int i = 0; i < EPT; ++i) {
                    if (!((done >> i) & 1u)) {
                        unsigned long long w = ld_relaxed_u64(src + pbase + i * 32);
                        if ((unsigned int)(w >> 32) == want) {
                            vals[i] = __uint_as_float((unsigned int)w);
                            done |= (1u << i);
                        }
                    }
                }
            } while (done != 0xFFu);
            #pragma unroll
            for (int i = 0; i < EPT; ++i) ssum += vals[i];
        }
        #pragma unroll
        for (int off = 16; off > 0; off >>= 1)
            ssum += __shfl_xor_sync(0xffffffffu, ssum, off);
        __syncthreads();                     // red_s free after main loop
        if (lane == 0) red_s[warp] = ssum;
        __syncthreads();
        if (tid == 0) {
            float tot = 0.f;
            #pragma unroll
            for (int w = 0; w < 8; ++w) tot += red_s[w];
            out[0] = -logf(tot);
        }
    }
}

// ---------------------------------------------------------------------------
// Launch wrapper. Inputs (metadata order): Pi_0 [2048] f32, A [2048*2048] f32,
// B [2048*8192] f32, se [8192] i32. Output: 1 x f32.
// ---------------------------------------------------------------------------
extern "C" void kernel_launch(void* const* d_in, const int* in_sizes, int n_in,
                              void* d_out, int out_size) {
    const float* Pi0 = (const float*)d_in[0];
    const float* A   = (const float*)d_in[1];
    const float* B   = (const float*)d_in[2];
    const int*   se  = (const int*)d_in[3];
    float*       out = (float*)d_out;

    (void)in_sizes; (void)n_in; (void)out_size;

    gather_bobs<<<2048, 256>>>(B, se);
    hmm_forward<<<N_BLOCKS, THREADS>>>(Pi0, A, out);
}

// round 10
// speedup vs baseline: 1.8850x; 1.8850x over previous
#include <cuda_runtime.h>
#include <cstdint>
#include <math.h>

// Problem constants (fixed shapes)
#define N_ST   2048
#define N_OBS  8192
#define T_LEN  8192

#define N_BLOCKS        128
#define COLS_PER_BLOCK  16          // 2048 / 128
#define THREADS         256
#define KITER           16          // row-PAIRS per thread (16 * 64 stripes * 2 = 2048)

// ---- persistent device scratch (no allocations allowed) ----
__device__ float              g_Bobs[(size_t)T_LEN * N_ST];   // 64 MB
__device__ float              g_alpha[2][N_ST];               // double-buffered alpha
__device__ unsigned long long g_count;                        // aggregated step counter
__device__ unsigned int       g_epoch;                        // bumped once per launch

// ---------------------------------------------------------------------------
// Sync + packed-f32x2 primitives
// ---------------------------------------------------------------------------
__device__ __forceinline__ unsigned long long ld_acquire_u64(const unsigned long long* p) {
    unsigned long long v;
    asm volatile("ld.acquire.gpu.global.u64 %0, [%1];" : "=l"(v) : "l"(p) : "memory");
    return v;
}
__device__ __forceinline__ void red_release_add_u64(unsigned long long* p, unsigned long long v) {
    asm volatile("red.release.gpu.global.add.u64 [%0], %1;" :: "l"(p), "l"(v) : "memory");
}
__device__ __forceinline__ unsigned long long pack_f32x2(float lo, float hi) {
    unsigned long long r;
    asm("mov.b64 %0, {%1, %2};" : "=l"(r) : "f"(lo), "f"(hi));
    return r;
}
__device__ __forceinline__ void unpack_f32x2(unsigned long long v, float& lo, float& hi) {
    asm("mov.b64 {%0, %1}, %2;" : "=f"(lo), "=f"(hi) : "l"(v));
}
__device__ __forceinline__ unsigned long long fma_f32x2(unsigned long long a,
                                                        unsigned long long b,
                                                        unsigned long long c) {
    unsigned long long d;
    asm("fma.rn.f32x2 %0, %1, %2, %3;" : "=l"(d) : "l"(a), "l"(b), "l"(c));
    return d;
}

// ---------------------------------------------------------------------------
// Kernel 1: gather emissions  Bobs[t][i] = B[i*N_OBS + se[t]]
// ---------------------------------------------------------------------------
__global__ void gather_bobs(const float* __restrict__ B, const int* __restrict__ se) {
    size_t idx    = (size_t)blockIdx.x * blockDim.x + threadIdx.x;
    size_t stride = (size_t)gridDim.x * blockDim.x;
    const size_t total = (size_t)T_LEN * N_ST;
    for (; idx < total; idx += stride) {
        int t = (int)(idx >> 11);
        int i = (int)(idx & (N_ST - 1));
        g_Bobs[idx] = B[(size_t)i * N_OBS + se[t]];
    }
}

// ---------------------------------------------------------------------------
// Kernel 2: persistent forward recursion (R3-proven skeleton).
// CTA b owns columns [16b, 16b+16). A-slice in registers as f32x2 row-pairs.
// Sync: single aggregated release-counter, polled by ONE thread per CTA.
// ---------------------------------------------------------------------------
__global__ void __launch_bounds__(THREADS, 1)
hmm_forward(const float* __restrict__ Pi0,
            const float* __restrict__ A,
            float* __restrict__ out)
{
    __shared__ __align__(16) float alpha_s[N_ST];
    __shared__ float red_s[8 * COLS_PER_BLOCK];   // [warp][16 cols]

    const int tid     = threadIdx.x;
    const int b       = blockIdx.x;
    const int colbase = b * COLS_PER_BLOCK;
    const int lane    = tid & 31;
    const int warp    = tid >> 5;
    const int c       = tid & 3;    // float4 column group (cols 4c..4c+3)
    const int q       = tid >> 2;   // pair-stripe id, 0..63

    // ---- one-time: load A slice into registers as (row 2p, row 2p+1) pairs ----
    unsigned long long A2[KITER][4];
    #pragma unroll
    for (int k = 0; k < KITER; ++k) {
        int p = q + (k << 6);
        float4 r0 = *(const float4*)(A + (size_t)(2 * p)     * N_ST + colbase + (c << 2));
        float4 r1 = *(const float4*)(A + (size_t)(2 * p + 1) * N_ST + colbase + (c << 2));
        A2[k][0] = pack_f32x2(r0.x, r1.x);
        A2[k][1] = pack_f32x2(r0.y, r1.y);
        A2[k][2] = pack_f32x2(r0.z, r1.z);
        A2[k][3] = pack_f32x2(r0.w, r1.w);
    }

    // ---- step 0: alpha0 = Pi0 * Bobs[0] ----
    if (tid < COLS_PER_BLOCK) {
        int i = colbase + tid;
        __stcg(&g_alpha[0][i], Pi0[i] * g_Bobs[i]);
    }
    __syncthreads();
    if (tid == 0)
        red_release_add_u64(&g_count, 1ull);   // release orders the stcg stores

    // ---- steps 1 .. T-1 ----
    for (int t = 1; t < T_LEN; ++t) {
        // emission weights (independent of alpha) -> issue early
        float bt = 0.0f;
        if (tid < COLS_PER_BLOCK)
            bt = __ldg(&g_Bobs[(size_t)t * N_ST + colbase + tid]);

        // wait until all 128 CTAs published step t-1 (single poller)
        const unsigned long long tgt = (unsigned long long)t * N_BLOCKS;
        if (tid == 0) {
            while (ld_acquire_u64(&g_count) < tgt) { }
        }
        __syncthreads();

        // stage alpha_{t-1} into SMEM (L2-coherent loads)
        {
            const float4* src = (const float4*)g_alpha[(t - 1) & 1];
            float4 v0 = __ldcv(src + tid);
            float4 v1 = __ldcv(src + tid + THREADS);
            ((float4*)alpha_s)[tid]           = v0;
            ((float4*)alpha_s)[tid + THREADS] = v1;
        }
        __syncthreads();

        // matvec partial with packed f32x2 FMAs:
        //   lo-lane accumulates row 2p, hi-lane row 2p+1
        unsigned long long acc0 = 0ull, acc1 = 0ull, acc2 = 0ull, acc3 = 0ull;
        #pragma unroll
        for (int k = 0; k < KITER; ++k) {
            int p = q + (k << 6);
            unsigned long long a2 = *(const unsigned long long*)&alpha_s[2 * p]; // LDS.64
            acc0 = fma_f32x2(a2, A2[k][0], acc0);
            acc1 = fma_f32x2(a2, A2[k][1], acc1);
            acc2 = fma_f32x2(a2, A2[k][2], acc2);
            acc3 = fma_f32x2(a2, A2[k][3], acc3);
        }
        float s0, s1, s2, s3;
        {
            float lo, hi;
            unpack_f32x2(acc0, lo, hi); s0 = lo + hi;
            unpack_f32x2(acc1, lo, hi); s1 = lo + hi;
            unpack_f32x2(acc2, lo, hi); s2 = lo + hi;
            unpack_f32x2(acc3, lo, hi); s3 = lo + hi;
        }

        // reduce across the 8 lanes sharing the same c (xor 4,8,16)
        #pragma unroll
        for (int off = 4; off < 32; off <<= 1) {
            s0 += __shfl_xor_sync(0xffffffffu, s0, off);
            s1 += __shfl_xor_sync(0xffffffffu, s1, off);
            s2 += __shfl_xor_sync(0xffffffffu, s2, off);
            s3 += __shfl_xor_sync(0xffffffffu, s3, off);
        }
        if (lane < 4) {   // lane == c here
            int o = (warp << 4) + (lane << 2);
            red_s[o + 0] = s0;
            red_s[o + 1] = s1;
            red_s[o + 2] = s2;
            red_s[o + 3] = s3;
        }
        __syncthreads();

        // final per-column sum over 8 warps, apply emission, publish
        if (tid < COLS_PER_BLOCK) {
            float sum = 0.f;
            #pragma unroll
            for (int w = 0; w < 8; ++w) sum += red_s[(w << 4) + tid];
            __stcg(&g_alpha[t & 1][colbase + tid], sum * bt);
        }
        __syncthreads();
        if (tid == 0)
            red_release_add_u64(&g_count, 1ull);   // release orders the stcg stores
    }

    // ---- final reduction + counter reset by CTA 0 ----
    if (b == 0) {
        const unsigned long long tgt = (unsigned long long)T_LEN * N_BLOCKS;
        if (tid == 0) {
            while (ld_acquire_u64(&g_count) < tgt) { }
        }
        __syncthreads();

        const float* src = g_alpha[(T_LEN - 1) & 1];
        float ssum = 0.f;
        for (int i = tid; i < N_ST; i += THREADS) ssum += __ldcv(&src[i]);
        #pragma unroll
        for (int off = 16; off > 0; off >>= 1)
            ssum += __shfl_xor_sync(0xffffffffu, ssum, off);
        if (lane == 0) red_s[warp] = ssum;
        __syncthreads();
        if (tid == 0) {
            float tot = 0.f;
            #pragma unroll
            for (int w = 0; w < 8; ++w) tot += red_s[w];
            out[0] = -logf(tot);
            // reset counter for the next graph replay (all increments observed)
            *((volatile unsigned long long*)&g_count) = 0ull;
        }
    }
}

// ---------------------------------------------------------------------------
// Launch wrapper. Inputs (metadata order): Pi_0 [2048] f32, A [2048*2048] f32,
// B [2048*8192] f32, se [8192] i32. Output: 1 x f32.
// ---------------------------------------------------------------------------
extern "C" void kernel_launch(void* const* d_in, const int* in_sizes, int n_in,
                              void* d_out, int out_size) {
    const float* Pi0 = (const float*)d_in[0];
    const float* A   = (const float*)d_in[1];
    const float* B   = (const float*)d_in[2];
    const int*   se  = (const int*)d_in[3];
    float*       out = (float*)d_out;

    (void)in_sizes; (void)n_in; (void)out_size;

    gather_bobs<<<2048, 256>>>(B, se);
    hmm_forward<<<N_BLOCKS, THREADS>>>(Pi0, A, out);
}